// round 1
// baseline (speedup 1.0000x reference)
#include <cuda_runtime.h>
#include <math.h>

#define N_NODES 32767
#define EMB 256
#define HDIM 256
#define H2 512
#define G4 2048   // 4*H2
#define VOCAB 32

// -------- scratch (device globals; zero-initialized at module load) --------
__device__ float g_xtab[VOCAB * G4];            // per-vocab x_proj table
__device__ float g_WhhT[H2 * G4];               // W_hh transposed: [k][j]
__device__ float g_H[(N_NODES + 1) * H2];       // row N_NODES = zero sentinel (never written)
__device__ float g_C[(N_NODES + 1) * H2];       // row N_NODES = zero sentinel
__device__ float g_gates[1024 * G4];            // gates scratch for small levels (n <= 512)

__device__ __forceinline__ float sigm(float x) { return 1.0f / (1.0f + expf(-x)); }

// -------- prep 1: x_tab[v][j] = dot(emb[v], W_ih[j]) + b_ih[j] + b_hh[j] --------
__global__ __launch_bounds__(256) void xtab_kernel(const float* __restrict__ emb,
                                                   const float* __restrict__ W_ih,
                                                   const float* __restrict__ b_ih,
                                                   const float* __restrict__ b_hh) {
    __shared__ float se[EMB];
    int v = blockIdx.x;
    int t = threadIdx.x;  // 256
    se[t] = emb[v * EMB + t];
    __syncthreads();
    #pragma unroll
    for (int m = 0; m < 8; m++) {
        int j = m * 256 + t;
        float acc = b_ih[j] + b_hh[j];
        const float4* wr = (const float4*)(W_ih + j * EMB);
        #pragma unroll 8
        for (int k4 = 0; k4 < EMB / 4; k4++) {
            float4 w = wr[k4];
            acc += w.x * se[k4 * 4 + 0] + w.y * se[k4 * 4 + 1]
                 + w.z * se[k4 * 4 + 2] + w.w * se[k4 * 4 + 3];
        }
        g_xtab[v * G4 + j] = acc;
    }
}

// -------- prep 2: transpose W_hh [2048,512] -> g_WhhT [512,2048] --------
__global__ void transpose_kernel(const float* __restrict__ W_hh) {
    __shared__ float tile[32][33];
    int j0 = blockIdx.x * 32;   // gate dim (2048)
    int k0 = blockIdx.y * 32;   // k dim (512)
    int tx = threadIdx.x, ty = threadIdx.y;  // (32, 8)
    #pragma unroll
    for (int r = 0; r < 32; r += 8)
        tile[ty + r][tx] = W_hh[(j0 + ty + r) * H2 + k0 + tx];
    __syncthreads();
    #pragma unroll
    for (int r = 0; r < 32; r += 8)
        g_WhhT[(k0 + ty + r) * G4 + j0 + tx] = tile[tx][ty + r];
}

// -------- big levels (n >= 1024): 8 nodes x all 2048 gates per CTA, fused epilogue --------
// gate index for (m, t): j = (m&3)*512 + (m>>2)*256 + t   (group g = m&3, half h = m>>2)
__global__ __launch_bounds__(256, 2) void big_level_kernel(
    const int* __restrict__ types, const int* __restrict__ a_idx,
    const int* __restrict__ b_idx, float* __restrict__ out, int s) {
    __shared__ float hbuf[8][H2];
    __shared__ int sa[8], sb[8], stype[8];
    int t = threadIdx.x;
    int base = s + blockIdx.x * 8;
    if (t < 8) {
        int i = base + t;
        sa[t] = a_idx[i];
        sb[t] = b_idx[i];
        stype[t] = types[i];
    }
    __syncthreads();
    // gather h = concat(H[a][:256], H[b][:256]) for 8 nodes
    #pragma unroll
    for (int it = 0; it < 16; it++) {
        int idx = it * 256 + t;
        int r = idx >> 9;
        int k = idx & 511;
        int child = (k < HDIM) ? sa[r] : sb[r];
        int kk = (k < HDIM) ? k : (k - HDIM);
        hbuf[r][k] = g_H[child * H2 + kk];
    }
    __syncthreads();

    float acc[8][8];
    #pragma unroll
    for (int r = 0; r < 8; r++) {
        const float* xt = g_xtab + stype[r] * G4;
        #pragma unroll
        for (int m = 0; m < 8; m++)
            acc[r][m] = xt[((m & 3) << 9) + ((m >> 2) << 8) + t];
    }

    for (int k = 0; k < H2; k += 4) {
        #pragma unroll
        for (int kk = 0; kk < 4; kk++) {
            const float* wrow = g_WhhT + (k + kk) * G4 + t;
            float w[8];
            #pragma unroll
            for (int m = 0; m < 8; m++)
                w[m] = wrow[((m & 3) << 9) + ((m >> 2) << 8)];
            float hv[8];
            #pragma unroll
            for (int r = 0; r < 8; r++) hv[r] = hbuf[r][k + kk];
            #pragma unroll
            for (int r = 0; r < 8; r++)
                #pragma unroll
                for (int m = 0; m < 8; m++)
                    acc[r][m] = fmaf(w[m], hv[r], acc[r][m]);
        }
    }

    // fused LSTM epilogue
    #pragma unroll
    for (int r = 0; r < 8; r++) {
        int i = base + r;
        #pragma unroll
        for (int h = 0; h < 2; h++) {
            int hid = (h << 8) + t;
            float ig = acc[r][h * 4 + 0];
            float fg = acc[r][h * 4 + 1];
            float gg = acc[r][h * 4 + 2];
            float og = acc[r][h * 4 + 3];
            int child = h ? sb[r] : sa[r];
            float c_old = g_C[child * H2 + t];
            float c_new = sigm(fg) * c_old + sigm(ig) * tanhf(gg);
            float h_new = sigm(og) * tanhf(c_new);
            g_C[i * H2 + hid] = c_new;
            g_H[i * H2 + hid] = h_new;
            out[i * H2 + hid] = h_new;
        }
    }
}

// -------- small levels (n <= 512): gate-split GEMM into scratch --------
__global__ __launch_bounds__(256) void small_gates_kernel(
    const int* __restrict__ types, const int* __restrict__ a_idx,
    const int* __restrict__ b_idx, int s, int n) {
    __shared__ float hbuf[4][H2];
    __shared__ int stype[4], svalid[4], sa4[4], sb4[4];
    int t = threadIdx.x;
    int base = s + blockIdx.x * 4;
    if (t < 4) {
        int i = base + t;
        int v = (i < s + n);
        svalid[t] = v;
        sa4[t] = v ? a_idx[i] : N_NODES;
        sb4[t] = v ? b_idx[i] : N_NODES;
        stype[t] = v ? types[i] : 0;
    }
    __syncthreads();
    #pragma unroll
    for (int it = 0; it < 8; it++) {
        int idx = it * 256 + t;
        int r = idx >> 9;
        int k = idx & 511;
        int child = (k < HDIM) ? sa4[r] : sb4[r];
        int kk = (k < HDIM) ? k : (k - HDIM);
        hbuf[r][k] = g_H[child * H2 + kk];
    }
    __syncthreads();
    int j = blockIdx.y * 256 + t;
    float acc[4];
    #pragma unroll
    for (int r = 0; r < 4; r++) acc[r] = g_xtab[stype[r] * G4 + j];
    #pragma unroll 4
    for (int k = 0; k < H2; k++) {
        float w = g_WhhT[k * G4 + j];
        #pragma unroll
        for (int r = 0; r < 4; r++) acc[r] = fmaf(w, hbuf[r][k], acc[r]);
    }
    #pragma unroll
    for (int r = 0; r < 4; r++)
        if (svalid[r]) g_gates[(blockIdx.x * 4 + r) * G4 + j] = acc[r];
}

__global__ __launch_bounds__(256) void small_epi_kernel(
    const int* __restrict__ a_idx, const int* __restrict__ b_idx,
    float* __restrict__ out, int s) {
    int i = s + blockIdx.x;
    int t = threadIdx.x;
    int a = a_idx[i], b = b_idx[i];
    const float* gr = g_gates + (size_t)blockIdx.x * G4;
    #pragma unroll
    for (int h = 0; h < 2; h++) {
        int hid = (h << 8) + t;
        float ig = gr[0 * 512 + hid];
        float fg = gr[1 * 512 + hid];
        float gg = gr[2 * 512 + hid];
        float og = gr[3 * 512 + hid];
        int child = h ? b : a;
        float c_old = g_C[child * H2 + t];
        float c_new = sigm(fg) * c_old + sigm(ig) * tanhf(gg);
        float h_new = sigm(og) * tanhf(c_new);
        g_C[i * H2 + hid] = c_new;
        g_H[i * H2 + hid] = h_new;
        out[i * H2 + hid] = h_new;
    }
}

extern "C" void kernel_launch(void* const* d_in, const int* in_sizes, int n_in,
                              void* d_out, int out_size) {
    const int* types   = (const int*)d_in[0];
    const int* a_idx   = (const int*)d_in[1];
    const int* b_idx   = (const int*)d_in[2];
    const float* emb   = (const float*)d_in[3];
    const float* W_ih  = (const float*)d_in[4];
    const float* W_hh  = (const float*)d_in[5];
    const float* b_ih  = (const float*)d_in[6];
    const float* b_hh  = (const float*)d_in[7];
    float* out = (float*)d_out;

    xtab_kernel<<<VOCAB, 256>>>(emb, W_ih, b_ih, b_hh);
    transpose_kernel<<<dim3(G4 / 32, H2 / 32), dim3(32, 8)>>>(W_hh);

    for (int d = 14; d >= 0; d--) {
        int n = 1 << d;
        int s = n - 1;
        if (n >= 1024) {
            big_level_kernel<<<n / 8, 256>>>(types, a_idx, b_idx, out, s);
        } else {
            small_gates_kernel<<<dim3((n + 3) / 4, 8), 256>>>(types, a_idx, b_idx, s, n);
            small_epi_kernel<<<n, 256>>>(a_idx, b_idx, out, s);
        }
    }
}